// round 13
// baseline (speedup 1.0000x reference)
#include <cuda_runtime.h>
#include <cstdint>

// Inverse 3D Haar synthesis — all-bulk (TMA) variant:
//   in  : [B=2, 8*16, T=8, H=128, W=128] fp32 (8 subbands of 16 channels)
//   out : [B=2, 16, 16, 256, 256] fp32
// out[b,g,2t+pt,2h+ph,2w+pw] = (1/8) * sum_s (-1)^(bt*pt+bh*ph+bw*pw) * x[...]
//
// CTA tile: 4 input h rows x full W for one (b,g,t).
//   Reads:  8x cp.async.bulk 2KB (each subband's 4 rows are contiguous).
//   Writes: 2x cp.async.bulk 8KB (each pt chunk: 8 output rows contiguous).
// Every DRAM transaction is a large sequential burst via the async proxy;
// L1/LSU only touches smem. Goal: fewer read/write turnarounds at the
// memory controller -> higher sustained mixed bandwidth.

__device__ __forceinline__ float2 f2add(float2 a, float2 b) {
    return make_float2(a.x + b.x, a.y + b.y);
}
__device__ __forceinline__ float2 f2sub(float2 a, float2 b) {
    return make_float2(a.x - b.x, a.y - b.y);
}

__device__ __forceinline__ uint32_t smem_u32(const void* p) {
    uint32_t a;
    asm("{ .reg .u64 t; cvta.to.shared.u64 t, %1; cvt.u32.u64 %0, t; }"
        : "=r"(a) : "l"(p));
    return a;
}

__global__ __launch_bounds__(256) void ihaar3d_kernel(const float* __restrict__ x,
                                                      float* __restrict__ out) {
    // Input stage: 8 subbands x 4 rows x 128 floats = 16KB.
    __shared__ __align__(16) float sin[8][4][128];
    // Output stage: 2 pt chunks x 8 rows x 256 floats = 16KB.
    __shared__ __align__(16) float sout[2][8][256];
    __shared__ __align__(8) uint64_t mbar;

    const int tid = threadIdx.x;
    const int w2 = tid & 63;   // w-pair within row (w0 = 2*w2)
    const int hr = tid >> 6;   // which of the 4 input h rows

    // CTA decode: [b(1)][g(4)][t(3)][h4(5)] -> 8192 CTAs.
    const int cta = blockIdx.x;
    const int h4 = cta & 31;
    const int t  = (cta >> 5) & 7;
    const int g  = (cta >> 8) & 15;
    const int b  = (cta >> 12) & 1;

    // input: [B, 128, 8, 128, 128]; subband stride 16 ch; 4 rows contiguous (2KB).
    const int SUB = 16 * 8 * 128 * 128;
    const int gbase = (((b * 128 + g) * 8 + t) * 128 + h4 * 4) * 128;

    const uint32_t mb = smem_u32(&mbar);
    if (tid == 0) {
        asm volatile("mbarrier.init.shared.b64 [%0], 1;" :: "r"(mb) : "memory");
    }
    __syncthreads();

    if (tid == 0) {
        asm volatile("mbarrier.arrive.expect_tx.shared.b64 _, [%0], %1;"
                     :: "r"(mb), "r"(16384u) : "memory");
#pragma unroll
        for (int s = 0; s < 8; ++s) {
            asm volatile(
                "cp.async.bulk.shared::cta.global.mbarrier::complete_tx::bytes "
                "[%0], [%1], %2, [%3];"
                :: "r"(smem_u32(&sin[s][0][0])), "l"(x + gbase + s * SUB),
                   "r"(2048u), "r"(mb) : "memory");
        }
    }

    // All threads wait for the 16KB to land (acquire orders the smem reads).
    {
        uint32_t done;
        asm volatile(
            "{ .reg .pred p;\n\t"
            "mbarrier.try_wait.parity.acquire.cta.shared::cta.b64 p, [%1], 0;\n\t"
            "selp.b32 %0, 1, 0, p; }"
            : "=r"(done) : "r"(mb) : "memory");
        while (!done) {
            asm volatile(
                "{ .reg .pred p;\n\t"
                "mbarrier.try_wait.parity.acquire.cta.shared::cta.b64 p, [%1], 0, 0x989680;\n\t"
                "selp.b32 %0, 1, 0, p; }"
                : "=r"(done) : "r"(mb) : "memory");
        }
    }

    // Per-thread butterfly on (hr, w0=2*w2) from smem.
    float2 v[8];
#pragma unroll
    for (int s = 0; s < 8; ++s)
        v[s] = *reinterpret_cast<const float2*>(&sin[s][hr][2 * w2]);

    // Stage 1: W butterfly (bit0).
    float2 ll_e = f2add(v[0], v[1]), ll_o = f2sub(v[0], v[1]);
    float2 lh_e = f2add(v[2], v[3]), lh_o = f2sub(v[2], v[3]);
    float2 hl_e = f2add(v[4], v[5]), hl_o = f2sub(v[4], v[5]);
    float2 hh_e = f2add(v[6], v[7]), hh_o = f2sub(v[6], v[7]);

    // Stage 2: H butterfly (bit1): index = ph.
    float2 le[2] = {f2add(ll_e, lh_e), f2sub(ll_e, lh_e)};
    float2 lo[2] = {f2add(ll_o, lh_o), f2sub(ll_o, lh_o)};
    float2 he[2] = {f2add(hl_e, hh_e), f2sub(hl_e, hh_e)};
    float2 ho[2] = {f2add(hl_o, hh_o), f2sub(hl_o, hh_o)};

    // Stage 3: T butterfly (bit2) + scale into contiguous output chunks.
    const float k = 0.125f;
#pragma unroll
    for (int pt = 0; pt < 2; ++pt) {
#pragma unroll
        for (int ph = 0; ph < 2; ++ph) {
            float2 e = pt == 0 ? f2add(le[ph], he[ph]) : f2sub(le[ph], he[ph]);
            float2 o = pt == 0 ? f2add(lo[ph], ho[ph]) : f2sub(lo[ph], ho[ph]);
            *reinterpret_cast<float4*>(&sout[pt][2 * hr + ph][4 * w2]) =
                make_float4(e.x * k, o.x * k, e.y * k, o.y * k);
        }
    }

    __syncthreads();
    asm volatile("fence.proxy.async.shared::cta;" ::: "memory");

    if (tid == 0) {
        // pt chunk: out[((b*16+g)*16 + 2t+pt)*65536 + 8*h4*256], 8KB contiguous.
        const int obase = (((b * 16 + g) * 16 + 2 * t) * 256 + 8 * h4) * 256;
        asm volatile("cp.async.bulk.global.shared::cta.bulk_group [%0], [%1], %2;"
                     :: "l"(out + obase), "r"(smem_u32(&sout[0][0][0])),
                        "r"(8192u) : "memory");
        asm volatile("cp.async.bulk.global.shared::cta.bulk_group [%0], [%1], %2;"
                     :: "l"(out + obase + 65536), "r"(smem_u32(&sout[1][0][0])),
                        "r"(8192u) : "memory");
        asm volatile("cp.async.bulk.commit_group;" ::: "memory");
        asm volatile("cp.async.bulk.wait_group 0;" ::: "memory");
    }
}

extern "C" void kernel_launch(void* const* d_in, const int* in_sizes, int n_in,
                              void* d_out, int out_size) {
    const float* x = (const float*)d_in[0];
    float* out = (float*)d_out;
    // 8192 CTAs x 256 threads; each CTA: 8x2KB bulk loads -> 2x8KB bulk stores.
    ihaar3d_kernel<<<8192, 256>>>(x, out);
}

// round 14
// speedup vs baseline: 1.0263x; 1.0263x over previous
#include <cuda_runtime.h>
#include <cstdint>

// Inverse 3D Haar synthesis (final):
//   in  : [B=2, 8*16, T=8, H=128, W=128] fp32 (8 subbands of 16 channels)
//   out : [B=2, 16, 16, 256, 256] fp32
// out[b,g,2t+pt,2h+ph,2w+pw] = (1/8) * sum_s (-1)^(bt*pt+bh*ph+bw*pw) * x[b, s*16+g, t, h, w]
// with s = 4*bt + 2*bh + bw.
//
// Thread mapping: lane owns 4 consecutive input w -> 8 CONTIGUOUS output
// floats per (pt,ph) row.
//   Loads : 8x LDG.128, 512B/warp fully dense, 8 independent streams (MLP=8).
//   Stores: 4x 256-bit st.global.v8, 1KB/warp fully dense.
// Workload is compulsory-DRAM-traffic bound (~255MB/replay @ ~5.9TB/s mixed
// r/w). Measured floor across 13 variants: policy hints, write-through,
// streaming, TMA bulk, persistence pinning are all no-ops on this traffic.

__device__ __forceinline__ float4 f4add(float4 a, float4 b) {
    return make_float4(a.x + b.x, a.y + b.y, a.z + b.z, a.w + b.w);
}
__device__ __forceinline__ float4 f4sub(float4 a, float4 b) {
    return make_float4(a.x - b.x, a.y - b.y, a.z - b.z, a.w - b.w);
}

// 256-bit store: interleave (e,o) pairs and scale by k.
__device__ __forceinline__ void st256(float* p, float4 e, float4 o, float k) {
    asm volatile(
        "st.global.v8.b32 [%0], {%1,%2,%3,%4,%5,%6,%7,%8};"
        :: "l"(p),
           "f"(e.x * k), "f"(o.x * k), "f"(e.y * k), "f"(o.y * k),
           "f"(e.z * k), "f"(o.z * k), "f"(e.w * k), "f"(o.w * k)
        : "memory");
}

__global__ __launch_bounds__(256) void ihaar3d_kernel(const float* __restrict__ x,
                                                      float* __restrict__ out) {
    // Decode: [b(1)][g(4)][t(3)][h(7)][w4(5)] bits -> 2^20 threads.
    const int idx = blockIdx.x * blockDim.x + threadIdx.x;
    const int w4 = idx & 31;
    const int h  = (idx >> 5) & 127;
    const int t  = (idx >> 12) & 7;
    const int g  = (idx >> 15) & 15;
    const int b  = (idx >> 19) & 1;

    const int w0 = w4 << 2;

    // input: [B, 128, 8, 128, 128]; subband stride = 16 channels. Offsets fit int32.
    const int SUB = 16 * 8 * 128 * 128;  // 2,097,152
    const int base = (((b * 128 + g) * 8 + t) * 128 + h) * 128 + w0;

    float4 v0 = *reinterpret_cast<const float4*>(x + base + 0 * SUB);  // lll
    float4 v1 = *reinterpret_cast<const float4*>(x + base + 1 * SUB);  // llh
    float4 v2 = *reinterpret_cast<const float4*>(x + base + 2 * SUB);  // lhl
    float4 v3 = *reinterpret_cast<const float4*>(x + base + 3 * SUB);  // lhh
    float4 v4 = *reinterpret_cast<const float4*>(x + base + 4 * SUB);  // hll
    float4 v5 = *reinterpret_cast<const float4*>(x + base + 5 * SUB);  // hlh
    float4 v6 = *reinterpret_cast<const float4*>(x + base + 6 * SUB);  // hhl
    float4 v7 = *reinterpret_cast<const float4*>(x + base + 7 * SUB);  // hhh

    // Stage 1: W butterfly (bit0).
    float4 ll_e = f4add(v0, v1), ll_o = f4sub(v0, v1);
    float4 lh_e = f4add(v2, v3), lh_o = f4sub(v2, v3);
    float4 hl_e = f4add(v4, v5), hl_o = f4sub(v4, v5);
    float4 hh_e = f4add(v6, v7), hh_o = f4sub(v6, v7);

    // Stage 2: H butterfly (bit1): index = ph.
    float4 le[2] = {f4add(ll_e, lh_e), f4sub(ll_e, lh_e)};
    float4 lo[2] = {f4add(ll_o, lh_o), f4sub(ll_o, lh_o)};
    float4 he[2] = {f4add(hl_e, hh_e), f4sub(hl_e, hh_e)};
    float4 ho[2] = {f4add(hl_o, hh_o), f4sub(hl_o, hh_o)};

    // Stage 3: T butterfly (bit2) + scale + dense 256-bit stores.
    // out: [2, 16, 16, 256, 256]; lane chunk = 8 contiguous floats at 8*w4.
    const float k = 0.125f;
    const int obase = (((b * 16 + g) * 16 + 2 * t) * 256 + 2 * h) * 256 + (w4 << 3);
    const int PT = 256 * 256;
    const int PH = 256;

#pragma unroll
    for (int pt = 0; pt < 2; ++pt) {
#pragma unroll
        for (int ph = 0; ph < 2; ++ph) {
            float4 e = pt == 0 ? f4add(le[ph], he[ph]) : f4sub(le[ph], he[ph]);
            float4 o = pt == 0 ? f4add(lo[ph], ho[ph]) : f4sub(lo[ph], ho[ph]);
            st256(out + obase + pt * PT + ph * PH, e, o, k);
        }
    }
}

extern "C" void kernel_launch(void* const* d_in, const int* in_sizes, int n_in,
                              void* d_out, int out_size) {
    const float* x = (const float*)d_in[0];
    float* out = (float*)d_out;
    // total threads = 2*16*8*128*32 = 1,048,576
    ihaar3d_kernel<<<4096, 256>>>(x, out);
}